// round 17
// baseline (speedup 1.0000x reference)
#include <cuda_runtime.h>
#include <cuda_fp16.h>
#include <cstdint>
#include <math.h>

#define Bb 2
#define Tt 2048
#define Hh 16
#define Mtot 4096
#define KDIM 1024

// ===========================================================================
// Helpers
// ===========================================================================
__device__ __forceinline__ uint32_t smem_u32(const void* p) {
    uint32_t a;
    asm("{ .reg .u64 t; cvta.to.shared.u64 t, %1; cvt.u32.u64 %0, t; }"
        : "=r"(a) : "l"(p));
    return a;
}
__device__ __forceinline__ void cp16(uint32_t dst, const void* src) {
    asm volatile("cp.async.cg.shared.global [%0], [%1], 16;" :: "r"(dst), "l"(src));
}
#define CP_COMMIT() asm volatile("cp.async.commit_group;" ::: "memory")
#define CP_WAIT0()  asm volatile("cp.async.wait_group 0;" ::: "memory")

__device__ __forceinline__ void ldm4(uint32_t* r, uint32_t a) {
    asm volatile("ldmatrix.sync.aligned.m8n8.x4.shared.b16 {%0,%1,%2,%3}, [%4];"
        : "=r"(r[0]), "=r"(r[1]), "=r"(r[2]), "=r"(r[3]) : "r"(a));
}
__device__ __forceinline__ void mma16816(float* d, const uint32_t* a,
                                         uint32_t b0, uint32_t b1) {
    asm volatile("mma.sync.aligned.m16n8k16.row.col.f32.f16.f16.f32 "
        "{%0,%1,%2,%3}, {%4,%5,%6,%7}, {%8,%9}, {%0,%1,%2,%3};"
        : "+f"(d[0]), "+f"(d[1]), "+f"(d[2]), "+f"(d[3])
        : "r"(a[0]), "r"(a[1]), "r"(a[2]), "r"(a[3]), "r"(b0), "r"(b1));
}

__device__ __forceinline__ uint32_t packhf(float a, float b) {
    __half2 t; t.x = __float2half(a); t.y = __float2half(b);
    return *(uint32_t*)&t;
}

// ===========================================================================
// Scratch (device globals) — everything single fp16
// ===========================================================================
__device__ __half g_e[(size_t)Mtot * KDIM];                 // embed
__device__ __half g_w[(size_t)4 * 1024 * 1024];             // W^T x4
__device__ __half g_q[(size_t)Mtot * KDIM];                 // Q (pre-scaled 0.125*log2e)
__device__ __half g_k[(size_t)Mtot * KDIM];                 // K
__device__ __half g_vt[(size_t)Mtot * KDIM];                // V^T [b][n][t]
__device__ __half g_z[(size_t)Mtot * KDIM];                 // Z
__device__ uint32_t g_mbits[(size_t)Bb * Tt * (Tt / 32)];

// ===========================================================================
// Prep kernels: prep_main (conv + trans4) on stream 0; pack_mask on side
// stream (no dependency on other kernels — overlaps gemm_qkv).
// ===========================================================================
__global__ void prep_main(const float* __restrict__ embed,
                          const float* __restrict__ W0, const float* __restrict__ W1,
                          const float* __restrict__ W2, const float* __restrict__ W3,
                          __half* __restrict__ e, __half* __restrict__ T)
{
    int blk = blockIdx.x;
    int tid = threadIdx.x;
    if (blk < 4096) {
        int i = blk * 256 + tid;
        float4 v = ((const float4*)embed)[i];
        ((uint32_t*)e)[2 * i]     = packhf(v.x, v.y);
        ((uint32_t*)e)[2 * i + 1] = packhf(v.z, v.w);
    } else {
        __shared__ float t[32][33];
        int b = blk - 4096;
        int z = b >> 10, rem = b & 1023;
        int bx = rem & 31, by = rem >> 5;
        const float* W = (z == 0) ? W0 : (z == 1) ? W1 : (z == 2) ? W2 : W3;
        size_t dbase = (size_t)z * 1024 * 1024;
        int tx = tid & 31, ty = tid >> 5;
        int x0 = bx * 32, y0 = by * 32;
        #pragma unroll
        for (int i = 0; i < 32; i += 8)
            t[ty + i][tx] = W[(size_t)(y0 + ty + i) * 1024 + x0 + tx];
        __syncthreads();
        #pragma unroll
        for (int i = 0; i < 32; i += 8) {
            float v = t[tx][ty + i];
            T[dbase + (size_t)(x0 + ty + i) * 1024 + y0 + tx] = __float2half(v);
        }
    }
}

__global__ void pack_mask_k(const int* __restrict__ m, uint32_t* __restrict__ bits) {
    int i = blockIdx.x * blockDim.x + threadIdx.x;
    uint32_t bal = __ballot_sync(0xffffffffu, m[i] != 0);
    if ((threadIdx.x & 31) == 0) bits[i >> 5] = bal;
}

// ===========================================================================
// GEMM core: 128x128 CTA tile, KC=64, 2-stage (unchanged)
// ===========================================================================
#define GSTR2 72
#define GAEL (128 * GSTR2)
#define GSTAGE (2 * GAEL)
#define GEMM_SMEM_BYTES (2 * GSTAGE * 2) // 73728 B

__device__ __forceinline__ void gemm_core(
    uint32_t sb, int tid, int lane, int wm, int wn,
    const __half* __restrict__ A, const __half* __restrict__ B,
    int m0, int n0, float acc[2][8][4])
{
    const __half* srcA = A + (size_t)m0 * KDIM;
    const __half* srcB = B + (size_t)n0 * KDIM;

    auto issue = [&](int ch, int buf) {
        uint32_t dbase = sb + (uint32_t)buf * (GSTAGE * 2);
        #pragma unroll
        for (int i = 0; i < 8; i++) {
            int idx = tid + i * 256;
            int t = idx >> 10;
            int r = (idx >> 3) & 127, c = idx & 7;
            const __half* src = (t ? srcB : srcA) + (size_t)r * KDIM + ch * 64 + c * 8;
            cp16(dbase + t * (GAEL * 2) + r * (GSTR2 * 2) + c * 16, src);
        }
        CP_COMMIT();
    };

    issue(0, 0);
    const int NC = KDIM / 64;
    for (int ch = 0; ch < NC; ch++) {
        CP_WAIT0();
        __syncthreads();
        if (ch + 1 < NC) issue(ch + 1, (ch + 1) & 1);

        uint32_t bb = sb + (uint32_t)(ch & 1) * (GSTAGE * 2);
        uint32_t tA = bb, tB = bb + GAEL * 2;
        #pragma unroll
        for (int ks = 0; ks < 4; ks++) {
            uint32_t ao = (uint32_t)(wm * 32 + (lane & 15)) * (GSTR2 * 2)
                        + ks * 32 + (lane >> 4) * 16;
            uint32_t a0[4], a1[4];
            ldm4(a0, tA + ao);
            ldm4(a1, tA + ao + 16 * (GSTR2 * 2));
            #pragma unroll
            for (int p = 0; p < 4; p++) {
                uint32_t bo = (uint32_t)(wn * 64 + p * 16 + (lane & 15)) * (GSTR2 * 2)
                            + ks * 32 + (lane >> 4) * 16;
                uint32_t bf[4];
                ldm4(bf, tB + bo);
                mma16816(acc[0][2 * p],     a0, bf[0], bf[2]);
                mma16816(acc[0][2 * p + 1], a0, bf[1], bf[3]);
                mma16816(acc[1][2 * p],     a1, bf[0], bf[2]);
                mma16816(acc[1][2 * p + 1], a1, bf[1], bf[3]);
            }
        }
    }
}

// Fused Q/K/V projections. z=0: Q (scaled 0.125*log2e); z=1: K; z=2: V^T.
#define VT_STR 136

__global__ __launch_bounds__(256, 2) void gemm_qkv(
    const __half* __restrict__ A, const __half* __restrict__ Wt,
    const float* __restrict__ bq, const float* __restrict__ bk,
    const float* __restrict__ bv,
    __half* __restrict__ q, __half* __restrict__ k, __half* __restrict__ vt)
{
    extern __shared__ __half sm[];
    uint32_t sb = smem_u32(sm);
    int tid = threadIdx.x, lane = tid & 31, w = tid >> 5;
    int wm = w & 3, wn = w >> 2;
    int m0 = blockIdx.y * 128, n0 = blockIdx.x * 128;
    int z = blockIdx.z;
    const size_t WSZ = (size_t)1024 * 1024;
    const __half* B = Wt + (size_t)z * WSZ;
    const float* bias = (z == 0) ? bq : (z == 1) ? bk : bv;

    float acc[2][8][4];
    #pragma unroll
    for (int mf = 0; mf < 2; mf++)
        #pragma unroll
        for (int na = 0; na < 8; na++)
            #pragma unroll
            for (int j = 0; j < 4; j++) acc[mf][na][j] = 0.0f;

    gemm_core(sb, tid, lane, wm, wn, A, B, m0, n0, acc);

    if (z == 0 || z == 1) {
        float scale = (z == 0) ? 0.125f * 1.44269504f : 1.0f;
        __half* O = (z == 0) ? q : k;
        #pragma unroll
        for (int mf = 0; mf < 2; mf++)
        #pragma unroll
        for (int na = 0; na < 8; na++) {
            int col = n0 + wn * 64 + na * 8 + (lane & 3) * 2;
            int rbase = m0 + wm * 32 + mf * 16 + (lane >> 2);
            float v0 = (acc[mf][na][0] + bias[col]) * scale;
            float v1 = (acc[mf][na][1] + bias[col + 1]) * scale;
            float v2 = (acc[mf][na][2] + bias[col]) * scale;
            float v3 = (acc[mf][na][3] + bias[col + 1]) * scale;
            *(uint32_t*)(O + (size_t)rbase * 1024 + col)       = packhf(v0, v1);
            *(uint32_t*)(O + (size_t)(rbase + 8) * 1024 + col) = packhf(v2, v3);
        }
    } else {
        __syncthreads();
        __half* tb = sm;
        #pragma unroll
        for (int mf = 0; mf < 2; mf++)
        #pragma unroll
        for (int na = 0; na < 8; na++) {
            int nloc = wn * 64 + na * 8 + (lane & 3) * 2;
            int mloc = wm * 32 + mf * 16 + (lane >> 2);
            float v0 = acc[mf][na][0] + bias[n0 + nloc];
            float v1 = acc[mf][na][1] + bias[n0 + nloc + 1];
            float v2 = acc[mf][na][2] + bias[n0 + nloc];
            float v3 = acc[mf][na][3] + bias[n0 + nloc + 1];
            tb[nloc * VT_STR + mloc]           = __float2half(v0);
            tb[(nloc + 1) * VT_STR + mloc]     = __float2half(v1);
            tb[nloc * VT_STR + mloc + 8]       = __float2half(v2);
            tb[(nloc + 1) * VT_STR + mloc + 8] = __float2half(v3);
        }
        __syncthreads();
        int bi = m0 >> 11, tbase = m0 & 2047;
        #pragma unroll
        for (int i = 0; i < 8; i++) {
            int idx = tid + i * 256;
            int n = idx >> 4, c = idx & 15;
            uint4 v = *(const uint4*)(tb + n * VT_STR + c * 8);
            *(uint4*)(vt + ((size_t)bi * 1024 + n0 + n) * 2048 + tbase + c * 8) = v;
        }
    }
}

// Output projection: fp32 straight to d_out.
__global__ __launch_bounds__(256, 2) void gemm_out(
    const __half* __restrict__ A, const __half* __restrict__ B,
    const float* __restrict__ bias, float* __restrict__ outF)
{
    extern __shared__ __half sm[];
    uint32_t sb = smem_u32(sm);
    int tid = threadIdx.x, lane = tid & 31, w = tid >> 5;
    int wm = w & 3, wn = w >> 2;
    int m0 = blockIdx.y * 128, n0 = blockIdx.x * 128;

    float acc[2][8][4];
    #pragma unroll
    for (int mf = 0; mf < 2; mf++)
        #pragma unroll
        for (int na = 0; na < 8; na++)
            #pragma unroll
            for (int j = 0; j < 4; j++) acc[mf][na][j] = 0.0f;

    gemm_core(sb, tid, lane, wm, wn, A, B, m0, n0, acc);

    #pragma unroll
    for (int mf = 0; mf < 2; mf++)
    #pragma unroll
    for (int na = 0; na < 8; na++) {
        int col = n0 + wn * 64 + na * 8 + (lane & 3) * 2;
        int rbase = m0 + wm * 32 + mf * 16 + (lane >> 2);
        float b0 = bias[col], b1 = bias[col + 1];
        *(float2*)(outF + (size_t)rbase * 1024 + col) =
            make_float2(acc[mf][na][0] + b0, acc[mf][na][1] + b1);
        *(float2*)(outF + (size_t)(rbase + 8) * 1024 + col) =
            make_float2(acc[mf][na][2] + b0, acc[mf][na][3] + b1);
    }
}

// ===========================================================================
// Attention — FA-2, single fp16; KV tile 128; pipelined halves; ex2 softmax.
// (unchanged from R16)
// ===========================================================================
#define ASTR 72
#define VSTR 136
#define AQ   (128 * ASTR)
#define AK   (128 * ASTR)
#define AV   (64 * VSTR)
#define ASTAGE (AK + AV)
#define ATTN_SMEM_BYTES ((AQ + 2 * ASTAGE) * 2)   // 90112 B

__global__ __launch_bounds__(256, 2) void attn_mma() {
    extern __shared__ __half sm[];
    uint32_t sb = smem_u32(sm);
    int tid = threadIdx.x, lane = tid & 31, w = tid >> 5;
    int q0 = blockIdx.x * 128;
    int b = blockIdx.y >> 4, hd = blockIdx.y & 15;

    uint32_t tQ = sb;
    const uint32_t kvb0 = sb + 2 * AQ;

    #pragma unroll
    for (int i = 0; i < 4; i++) {
        int idx = tid + i * 256;
        int row = idx >> 3, c = idx & 7;
        cp16(tQ + row * (ASTR * 2) + c * 16,
             g_q + (size_t)(b * Tt + q0 + row) * 1024 + hd * 64 + c * 8);
    }

    auto issueKV = [&](int kt, int buf) {
        uint32_t dbase = kvb0 + (uint32_t)buf * (ASTAGE * 2);
        int kv0 = kt * 128;
        #pragma unroll
        for (int i = 0; i < 8; i++) {
            int idx = tid + i * 256;
            if (idx < 1024) {
                int r = idx >> 3, c = idx & 7;
                cp16(dbase + r * (ASTR * 2) + c * 16,
                     g_k + (size_t)(b * Tt + kv0 + r) * 1024 + hd * 64 + c * 8);
            } else {
                int j = idx - 1024;
                int r = j >> 4, c = j & 15;
                cp16(dbase + AK * 2 + r * (VSTR * 2) + c * 16,
                     g_vt + (size_t)(b * 1024 + hd * 64 + r) * Tt + kv0 + c * 8);
            }
        }
        CP_COMMIT();
    };

    float o[8][4];
    #pragma unroll
    for (int t = 0; t < 8; t++)
        #pragma unroll
        for (int j = 0; j < 4; j++) o[t][j] = 0.0f;
    float lacc0 = 0.0f, lacc1 = 0.0f;
    uint32_t qf[4][4];

    int rowg = b * Tt + q0 + w * 16 + (lane >> 2);

    issueKV(0, 0);

    float s[8][4];
    uint32_t af[4][4];

    for (int kt = 0; kt < 16; kt++) {
        CP_WAIT0();
        __syncthreads();
        if (kt + 1 < 16) issueKV(kt + 1, (kt + 1) & 1);
        if (kt == 0) {
            #pragma unroll
            for (int ks = 0; ks < 4; ks++) {
                uint32_t ao = (uint32_t)(w * 16 + (lane & 15)) * (ASTR * 2)
                            + ks * 32 + (lane >> 4) * 16;
                ldm4(qf[ks], tQ + ao);
            }
        }

        uint32_t kb = kvb0 + (uint32_t)(kt & 1) * (ASTAGE * 2);
        uint32_t tK = kb, tV = kb + AK * 2;

        auto computeS = [&](int half) {
            #pragma unroll
            for (int t = 0; t < 8; t++)
                #pragma unroll
                for (int j = 0; j < 4; j++) s[t][j] = 0.0f;
            #pragma unroll
            for (int ks = 0; ks < 4; ks++) {
                #pragma unroll
                for (int pp = 0; pp < 2; pp++) {
                    uint32_t bo0 = (uint32_t)(half * 64 + 2 * pp * 16 + (lane & 15))
                                   * (ASTR * 2) + ks * 32 + (lane >> 4) * 16;
                    uint32_t bo1 = bo0 + 16 * (ASTR * 2);
                    uint32_t k0[4], k1[4];
                    ldm4(k0, tK + bo0); ldm4(k1, tK + bo1);
                    mma16816(s[4 * pp + 0], qf[ks], k0[0], k0[2]);
                    mma16816(s[4 * pp + 1], qf[ks], k0[1], k0[3]);
                    mma16816(s[4 * pp + 2], qf[ks], k1[0], k1[2]);
                    mma16816(s[4 * pp + 3], qf[ks], k1[1], k1[3]);
                }
            }
        };

        auto softmax = [&](int half) {
            uint32_t mw0 = g_mbits[(size_t)rowg * 64 + kt * 4 + 2 * half];
            uint32_t mw1 = g_mbits[(size_t)rowg * 64 + kt * 4 + 2 * half + 1];
            uint32_t mw2 = g_mbits[(size_t)(rowg + 8) * 64 + kt * 4 + 2 * half];
            uint32_t mw3 = g_mbits[(size_t)(rowg + 8) * 64 + kt * 4 + 2 * half + 1];
            #pragma unroll
            for (int t = 0; t < 8; t++) {
                int cb = 8 * t + 2 * (lane & 3);
                uint32_t wa = (t < 4) ? mw0 : mw1;
                uint32_t wb = (t < 4) ? mw2 : mw3;
                int bit = cb & 31;
                float p0 = ((wa >> bit) & 1u)       ? exp2f(s[t][0]) : 0.0f;
                float p1 = ((wa >> (bit + 1)) & 1u) ? exp2f(s[t][1]) : 0.0f;
                float p2 = ((wb >> bit) & 1u)       ? exp2f(s[t][2]) : 0.0f;
                float p3 = ((wb >> (bit + 1)) & 1u) ? exp2f(s[t][3]) : 0.0f;
                lacc0 += p0 + p1;
                lacc1 += p2 + p3;
                int u = t >> 1, k = (t & 1) * 2;
                af[u][k]     = packhf(p0, p1);
                af[u][k + 1] = packhf(p2, p3);
            }
        };

        auto doPV = [&](int half) {
            #pragma unroll
            for (int u = 0; u < 4; u++) {
                #pragma unroll
                for (int pp = 0; pp < 2; pp++) {
                    uint32_t bo0 = (uint32_t)(2 * pp * 16 + (lane & 15)) * (VSTR * 2)
                                 + half * 128 + u * 32 + (lane >> 4) * 16;
                    uint32_t bo1 = bo0 + 16 * (VSTR * 2);
                    uint32_t v0[4], v1[4];
                    ldm4(v0, tV + bo0); ldm4(v1, tV + bo1);
                    mma16816(o[4 * pp + 0], af[u], v0[0], v0[2]);
                    mma16816(o[4 * pp + 1], af[u], v0[1], v0[3]);
                    mma16816(o[4 * pp + 2], af[u], v1[0], v1[2]);
                    mma16816(o[4 * pp + 3], af[u], v1[1], v1[3]);
                }
            }
        };

        computeS(0);
        softmax(0);
        computeS(1);
        doPV(0);
        softmax(1);
        doPV(1);
    }

    lacc0 += __shfl_xor_sync(0xffffffffu, lacc0, 1);
    lacc0 += __shfl_xor_sync(0xffffffffu, lacc0, 2);
    lacc1 += __shfl_xor_sync(0xffffffffu, lacc1, 1);
    lacc1 += __shfl_xor_sync(0xffffffffu, lacc1, 2);
    float inv0 = 1.0f / lacc0, inv1 = 1.0f / lacc1;

    int row = q0 + w * 16 + (lane >> 2);
    #pragma unroll
    for (int t = 0; t < 8; t++) {
        int col = hd * 64 + 8 * t + 2 * (lane & 3);
        size_t o0 = (size_t)(b * Tt + row) * 1024 + col;
        size_t o1 = (size_t)(b * Tt + row + 8) * 1024 + col;
        *(uint32_t*)(g_z + o0) = packhf(o[t][0] * inv0, o[t][1] * inv0);
        *(uint32_t*)(g_z + o1) = packhf(o[t][2] * inv1, o[t][3] * inv1);
    }
}

// ===========================================================================
extern "C" void kernel_launch(void* const* d_in, const int* in_sizes, int n_in,
                              void* d_out, int out_size)
{
    const float* embed = (const float*)d_in[0];
    const int*   mask  = (const int*)d_in[1];
    const float* Wq = (const float*)d_in[2];
    const float* bq = (const float*)d_in[3];
    const float* Wk = (const float*)d_in[4];
    const float* bk = (const float*)d_in[5];
    const float* Wv = (const float*)d_in[6];
    const float* bv = (const float*)d_in[7];
    const float* Wz = (const float*)d_in[8];
    const float* bz = (const float*)d_in[9];
    float* out = (float*)d_out;

    __half *e, *wt, *q, *k, *vt, *z;
    uint32_t* mbits;
    cudaGetSymbolAddress((void**)&e, g_e);
    cudaGetSymbolAddress((void**)&wt, g_w);
    cudaGetSymbolAddress((void**)&q, g_q);
    cudaGetSymbolAddress((void**)&k, g_k);
    cudaGetSymbolAddress((void**)&vt, g_vt);
    cudaGetSymbolAddress((void**)&z, g_z);
    cudaGetSymbolAddress((void**)&mbits, g_mbits);

    cudaFuncSetAttribute(gemm_qkv, cudaFuncAttributeMaxDynamicSharedMemorySize,
                         GEMM_SMEM_BYTES);
    cudaFuncSetAttribute(gemm_out, cudaFuncAttributeMaxDynamicSharedMemorySize,
                         GEMM_SMEM_BYTES);
    cudaFuncSetAttribute(attn_mma, cudaFuncAttributeMaxDynamicSharedMemorySize,
                         ATTN_SMEM_BYTES);

    const size_t WSZ = (size_t)1024 * 1024;

    // Side stream for mask packing (created once, on the first — non-captured —
    // correctness call; reused identically in every subsequent call).
    static cudaStream_t s2 = nullptr;
    static cudaEvent_t evFork = nullptr, evJoin = nullptr;
    if (s2 == nullptr) {
        cudaStreamCreateWithFlags(&s2, cudaStreamNonBlocking);
        cudaEventCreateWithFlags(&evFork, cudaEventDisableTiming);
        cudaEventCreateWithFlags(&evJoin, cudaEventDisableTiming);
    }

    // Fork: pack_mask depends only on the mask input; overlap it with
    // prep_main + gemm_qkv (compute-bound, DRAM ~2%).
    cudaEventRecord(evFork, 0);
    cudaStreamWaitEvent(s2, evFork, 0);
    pack_mask_k<<<32768, 256, 0, s2>>>(mask, mbits);
    cudaEventRecord(evJoin, s2);

    // Main stream: conv + weight transposes, then Q/K/V projections.
    prep_main<<<8192, 256>>>(embed, Wq, Wk, Wv, Wz, e, wt);
    gemm_qkv<<<dim3(8, 32, 3), 256, GEMM_SMEM_BYTES>>>(
        e, wt, bq, bk, bv, q, k, vt);

    // Join: attention needs the packed mask.
    cudaStreamWaitEvent(0, evJoin, 0);
    attn_mma<<<dim3(16, 32), 256, ATTN_SMEM_BYTES>>>();

    // Output projection -> d_out (fp32)
    gemm_out<<<dim3(8, 32), 256, GEMM_SMEM_BYTES>>>(
        z, wt + 3 * WSZ, bz, out);
}